// round 8
// baseline (speedup 1.0000x reference)
#include <cuda_runtime.h>
#include <cstdint>

#define FULL 0xffffffffu
constexpr int NQ  = 8;
constexpr int IND = 512;
constexpr int WPB = 8;            // warps per block
constexpr int TPB = WPB * 32;
constexpr int M4  = 2;            // batch elements per warp pass
constexpr int GRID = 296;         // 2 blocks/SM on 148 SMs
constexpr int STAGE_F4 = M4 * 128;                  // 256 float4 (4KB) per stage
constexpr size_t DYN_SMEM = (size_t)WPB * 2 * STAGE_F4 * sizeof(float4);  // 64KB

__device__ __forceinline__ void cp_async16(void* smem_dst, const void* gmem_src) {
    unsigned int s = (unsigned int)__cvta_generic_to_shared(smem_dst);
    asm volatile("cp.async.cg.shared.global [%0], [%1], 16;" :: "r"(s), "l"(gmem_src));
}
__device__ __forceinline__ void cp_commit() {
    asm volatile("cp.async.commit_group;");
}
__device__ __forceinline__ void cp_wait1() {
    asm volatile("cp.async.wait_group 1;");
}

__global__ __launch_bounds__(TPB, 2)
void vqc_kernel(const float* __restrict__ h,
                const float* __restrict__ W,
                const float* __restrict__ bpre,
                const float* __restrict__ wts,
                float* __restrict__ out,
                int B)
{
    extern __shared__ float4 Hbuf[];            // [WPB][2][STAGE_F4]
    __shared__ float4 Wsh[NQ * IND / 4];        // 16 KB
    __shared__ float4 Msh[NQ][2];
    __shared__ float  Bsh[NQ];

    const int tid  = threadIdx.x;
    const int lane = tid & 31;
    const int wrp  = tid >> 5;

    // Stage W_pre into shared (coalesced)
    #pragma unroll
    for (int k = 0; k < (NQ * IND / 4) / TPB; ++k)
        Wsh[tid + k * TPB] = reinterpret_cast<const float4*>(W)[tid + k * TPB];

    // Batch-independent gate matrices M_w = Rz(g)*Ry(b)*Rx(a)
    if (tid < NQ) {
        Bsh[tid] = bpre[tid];
        float al = 0.5f * wts[tid * 3 + 0];
        float be = 0.5f * wts[tid * 3 + 1];
        float ga = 0.5f * wts[tid * 3 + 2];
        float sa, ca, sb, cb, sg, cg;
        sincosf(al, &sa, &ca);
        sincosf(be, &sb, &cb);
        sincosf(ga, &sg, &cg);
        float r00r =  cb * ca, r00i =  sb * sa;
        float r01r = -sb * ca, r01i = -cb * sa;
        float r10r =  sb * ca, r10i = -cb * sa;
        float r11r =  cb * ca, r11i = -sb * sa;
        Msh[tid][0] = make_float4(r00r * cg + r00i * sg,
                                  r00i * cg - r00r * sg,
                                  r01r * cg + r01i * sg,
                                  r01i * cg - r01r * sg);
        Msh[tid][1] = make_float4(r10r * cg - r10i * sg,
                                  r10i * cg + r10r * sg,
                                  r11r * cg - r11i * sg,
                                  r11i * cg + r11r * sg);
    }
    __syncthreads();

    const int lw = lane & 15;     // position within half-warp
    const int w  = lw >> 1;       // qubit owned by this lane after reduction
    const int m  = lane & 1;      // element-within-pass owned by this lane

    float4* const myH = Hbuf + wrp * 2 * STAGE_F4;
    const int STEP = GRID * WPB * M4;                 // elements per sweep

    // ---- prefetch first stage ----
    int e0 = (blockIdx.x * WPB + wrp) * M4;
    if (e0 < B) {
        const float4* hr = reinterpret_cast<const float4*>(h) + (size_t)e0 * (IND / 4);
        #pragma unroll
        for (int i = 0; i < M4 * 4; ++i)
            cp_async16(&myH[i * 32 + lane], &hr[i * 32 + lane]);
    }
    cp_commit();

    int buf = 0;
    for (; e0 < B; e0 += STEP, buf ^= 1) {
        // ---- prefetch next stage while computing this one ----
        int en = e0 + STEP;
        if (en < B) {
            const float4* hr = reinterpret_cast<const float4*>(h) + (size_t)en * (IND / 4);
            float4* dst = myH + (buf ^ 1) * STAGE_F4;
            #pragma unroll
            for (int i = 0; i < M4 * 4; ++i)
                cp_async16(&dst[i * 32 + lane], &hr[i * 32 + lane]);
        }
        cp_commit();
        cp_wait1();                    // current stage ready

        const float4* hs = myH + buf * STAGE_F4;

        // ---------- GEMM: r[o*2+mm] = <h[e0+mm], W[o]> (lane's K-slice) ----------
        float r[16];
        #pragma unroll
        for (int i = 0; i < 16; ++i) r[i] = 0.f;

        #pragma unroll
        for (int k = 0; k < 4; ++k) {
            float4 hv[M4];
            #pragma unroll
            for (int mm = 0; mm < M4; ++mm)
                hv[mm] = hs[mm * 128 + k * 32 + lane];
            #pragma unroll
            for (int o = 0; o < NQ; ++o) {
                float4 wv = Wsh[o * (IND / 4) + k * 32 + lane];
                #pragma unroll
                for (int mm = 0; mm < M4; ++mm) {
                    r[o * 2 + mm] = fmaf(hv[mm].x, wv.x, fmaf(hv[mm].y, wv.y,
                                    fmaf(hv[mm].z, wv.z, fmaf(hv[mm].w, wv.w, r[o * 2 + mm]))));
                }
            }
        }

        // ---------- reduce: fold half-warps, then 4-level exchange tree ----------
        #pragma unroll
        for (int j = 0; j < 16; ++j)
            r[j] += __shfl_xor_sync(FULL, r[j], 16);
        #pragma unroll
        for (int s = 3; s >= 0; --s) {
            const int d = 1 << s;
            const bool hi = (lane >> s) & 1;
            #pragma unroll
            for (int j = 0; j < d; ++j) {
                float keep = hi ? r[j + d] : r[j];
                float send = hi ? r[j] : r[j + d];
                keep += __shfl_xor_sync(FULL, send, d);
                r[j] = keep;
            }
        }
        float a = r[0];                // pre-activation for (qubit w, elem m); dup in upper half

        // ---------- single-qubit state & Pauli expectations ----------
        float t = tanhf(a + Bsh[w]) * 1.57079632679489662f;
        t = fminf(fmaxf(t, -3.14159265358979f), 3.14159265358979f);
        float s, c;
        sincosf(0.5f * t, &s, &c);
        float4 m0 = Msh[w][0], m1 = Msh[w][1];
        float v0r = m0.x * c + m0.z * s, v0i = m0.y * c + m0.w * s;
        float v1r = m1.x * c + m1.z * s, v1i = m1.y * c + m1.w * s;
        float x = 2.f * (v0r * v1r + v0i * v1i);
        float y = 2.f * (v0r * v1i - v0i * v1r);
        float z = (v0r * v0r + v0i * v0i) - (v1r * v1r + v1i * v1i);

        // ---------- product scans over the stride-2 lane comb (8 qubits) ----------
        float P = z;                   // inclusive prefix z0..zw
        float G = (w >= 2) ? z : 1.f;  // prefix of z restricted to w>=2
        #pragma unroll
        for (int d = 1; d < 8; d <<= 1) {
            float tp = __shfl_up_sync(FULL, P, 2 * d);
            float tg = __shfl_up_sync(FULL, G, 2 * d);
            if (w >= d) { P *= tp; G *= tg; }
        }
        float Pexc  = __shfl_up_sync(FULL, P, 2);                   // z0..z_{w-1}
        float xnext = __shfl_sync(FULL, x, m + 2 * ((w + 1) & 7));  // x_{w+1 mod 8}
        float x1    = __shfl_sync(FULL, x, m + 2);
        float y0    = __shfl_sync(FULL, y, m);
        float y1    = __shfl_sync(FULL, y, m + 2);
        float z1    = __shfl_sync(FULL, z, m + 2);
        float G6    = __shfl_sync(FULL, G, m + 12);                 // z2..z6
        float G7    = __shfl_sync(FULL, G, m + 14);                 // z2..z7

        // ---------- assemble the 3 observables this lane owns ----------
        float X = (w == 7) ? (x * xnext * x1) : (x * xnext);
        float Y, Z;
        if (w == 0)      { Y = x * y1 * G7;            Z = z1 * G7; }
        else if (w == 7) { Y = -y0 * y1 * G6 * y;      Z = P; }
        else             { Y = Pexc * y * xnext;       Z = P; }

        // ---------- normalize over the 24 outputs of this element ----------
        float ss = X * X + Y * Y + Z * Z;
        ss += __shfl_xor_sync(FULL, ss, 2);
        ss += __shfl_xor_sync(FULL, ss, 4);
        ss += __shfl_xor_sync(FULL, ss, 8);
        float inv = 1.f / fmaxf(sqrtf(ss), 1e-12f);

        int e = e0 + m;
        if (lane < 16 && e < B) {
            float* op = out + (size_t)e * 24 + 3 * w;
            op[0] = X * inv;
            op[1] = Y * inv;
            op[2] = Z * inv;
        }
    }
}

extern "C" void kernel_launch(void* const* d_in, const int* in_sizes, int n_in,
                              void* d_out, int out_size)
{
    const float* h    = (const float*)d_in[0];
    const float* W    = (const float*)d_in[1];
    const float* bpre = (const float*)d_in[2];
    const float* wts  = (const float*)d_in[3];
    float* out        = (float*)d_out;

    int B = in_sizes[0] / IND;                      // 16384

    static bool attr_done = false;                  // idempotent attribute raise
    if (!attr_done) {
        cudaFuncSetAttribute(vqc_kernel,
                             cudaFuncAttributeMaxDynamicSharedMemorySize,
                             (int)DYN_SMEM);
        attr_done = true;
    }
    vqc_kernel<<<GRID, TPB, DYN_SMEM>>>(h, W, bpre, wts, out, B);
}